// round 11
// baseline (speedup 1.0000x reference)
#include <cuda_runtime.h>

// Adaptive threshold spike encoding — FINAL (measured machine floor, R10 best:
// kernel 41.63 us, wall 45.50 us, 5.22 TB/s DRAM).
// x: [B=32, F=65536] f32.  out: [B=32, T=32, F=65536] f32.
//
// Closed model, 10 rounds / 6 configs (STG / STG.cs / TMA bulk / persistent /
// 512-thr blocks / throttled replay):
//   - Fixed traffic: 256 MB write + 8 MB read (output bytes set by problem).
//   - Binding resource: LTS write path (SM-clock domain). Each output byte
//     transits L2 twice (store fill + dirty writeback): 520 MB / 41.6 us
//     ~= 12.5 TB/s ~= path-independent ~6300 B/cyc LTS cap at NAT clock.
//   - Evidence: STG == STG.cs == TMA bulk within 0.5 us (no GMEM store path
//     bypasses L2 on sm_103a); DVFS-throttled run slowed proportionally to
//     SM clock at identical cycle count (a DRAM-device bound would not);
//     occupancy 51-95% / issue 12-35% / block & grid shape: no effect.
//   => ~80K cycles (~42 us kernel) is the hard floor for this op on GB300.
//
// Shape: 2048 blocks x 256 threads, one float4 per thread, 32 regs,
// exact-fit grid (no bounds check), coalesced STG.128 evict-first stores,
// fully unrolled 32-timestep loop (pure FFMA/FSEL recurrence, no spills).

#define TIMESTEPS 32
#define F_DIM 65536
#define F4_DIM (F_DIM / 4)      // 16384 float4 per feature row
#define RATE 0.1f
#define OMR 0.9f
#define THR0 0.5f
#define THREADS 256

__global__ __launch_bounds__(THREADS)
void adaptive_threshold_kernel(const float4* __restrict__ x,
                               float4* __restrict__ out) {
    int i = blockIdx.x * THREADS + threadIdx.x;   // float4 index (exact fit)

    float4 xv = __ldcs(&x[i]);

    // element index -> (batch, feature4)
    int e  = i << 2;                 // element index of lane 0 of this float4
    int b  = e >> 16;                // batch = e / 65536
    int f4 = (e & (F_DIM - 1)) >> 2; // float4 slot within the feature row

    float xx[4] = {xv.x, xv.y, xv.z, xv.w};
    float ad[4], acc[4], thr[4];
#pragma unroll
    for (int l = 0; l < 4; l++) {
        ad[l]  = RATE * fabsf(xx[l]);
        acc[l] = 0.0f;
        thr[l] = THR0;
    }

    // out[b][t][f]: base of this (b, f4) column, stride F4_DIM per timestep
    float4* ob = out + (size_t)b * (TIMESTEPS * F4_DIM) + f4;

#pragma unroll
    for (int t = 0; t < TIMESTEPS; t++) {
        float s[4];
#pragma unroll
        for (int l = 0; l < 4; l++) {
            acc[l] = acc[l] + xx[l];
            bool m = (acc[l] >= thr[l]);
            s[l]   = m ? 1.0f : 0.0f;
            acc[l] = m ? 0.0f : acc[l];
            thr[l] = thr[l] * OMR + ad[l];
        }
        float4 sv;
        sv.x = s[0]; sv.y = s[1]; sv.z = s[2]; sv.w = s[3];
        __stcs(ob + (size_t)t * F4_DIM, sv);
    }
}

extern "C" void kernel_launch(void* const* d_in, const int* in_sizes, int n_in,
                              void* d_out, int out_size) {
    const float4* x = (const float4*)d_in[0];
    float4* out = (float4*)d_out;
    int n4 = in_sizes[0] / 4;              // 524,288 — divisible by THREADS
    int blocks = n4 / THREADS;             // 2048
    adaptive_threshold_kernel<<<blocks, THREADS>>>(x, out);
}